// round 16
// baseline (speedup 1.0000x reference)
#include <cuda_runtime.h>

// Dense_RBS_density_3D: rho_out = W rho W^T, W = 39 sparse Givens layers
// (38 disjoint 2x2 column rotations each) on the C(40,2)=780-dim basis.
// K(M) = (M W^T)^T = W M^T applied twice => W rho W^T. Two launches with a
// private __device__ scratch between.
//
// R16 vs R15 (same geometry: float2 row-pairing, table-free walk, frontier
// carry, 15 rotate warps, 30-row tiles, 512 thr, 2 CTAs/SM):
// NO STAGING LOAD. B-phase j-reads (and gate-0 i-reads, and the {0,1}
// special) always consume ORIGINAL input values (their states' qubits are
// both > g, untouched by earlier gates) -> read them straight from gmem via
// a 3-deep register prefetch pipeline driven by a second walk offset running
// 3 gates ahead. Removes stage-STS + B-LDS = 2 of 6 smem ops per element
// (~25% of block L1tex wavefronts). A-phase/flush/store smem paths unchanged;
// every position is rotate-written before the store (A-writes cover b<=38,
// flushes cover {a,a+1} and b=39).

#define DD      780
#define NGATES  39
#define NBATCH  64
#define RROWS   30            // rows per tile
#define NPR     15            // pair-rows (float2 lanes)
#define NTILES  26            // 780 / 30
#define STRIDE2 781           // float2 stride per pair-row (odd)
#define THREADS 512
#define NITEMS  (NPR * DD)    // 11700 store items
#define PFD     3             // prefetch depth (gates ahead)

__device__ float g_tmp[(size_t)NBATCH * DD * DD];  // 155.7 MB scratch

typedef unsigned long long u64;

__device__ __forceinline__ u64 f2pack(float lo, float hi) {
    u64 r; asm("mov.b64 %0, {%1, %2};" : "=l"(r) : "f"(lo), "f"(hi)); return r;
}
__device__ __forceinline__ void f2unpack(float& lo, float& hi, u64 v) {
    asm("mov.b64 {%0, %1}, %2;" : "=f"(lo), "=f"(hi) : "l"(v));
}
__device__ __forceinline__ u64 f2mul(u64 a, u64 b) {
    u64 r; asm("mul.rn.f32x2 %0, %1, %2;" : "=l"(r) : "l"(a), "l"(b)); return r;
}
__device__ __forceinline__ u64 f2fma(u64 a, u64 b, u64 c) {
    u64 r; asm("fma.rn.f32x2 %0, %1, %2, %3;" : "=l"(r) : "l"(a), "l"(b), "l"(c));
    return r;
}

__device__ __forceinline__ void rbs_body(const float* __restrict__ in,
                                         float* __restrict__ out,
                                         const float* __restrict__ angles) {
    extern __shared__ u64 tile2[];                  // NPR * STRIDE2 float2
    __shared__ u64 s_cs[NGATES];                    // packed (cos, sin)

    const int tid  = threadIdx.x;
    const int w    = tid >> 5;
    const int lane = tid & 31;
    const int b    = blockIdx.x / NTILES;
    const int t    = blockIdx.x - b * NTILES;
    const int r0   = t * RROWS;

    if (tid < NGATES) {
        float th = angles[tid];
        s_cs[tid] = f2pack(cosf(th), sinf(th));
    }
    __syncthreads();                                // trig table visible

    const float* src = in + (size_t)b * DD * DD + (size_t)r0 * DD;

    if (w < NPR) {
        const float* p0 = src + (size_t)(2 * w) * DD;
        const float* p1 = p0 + DD;
        u64* rp = &tile2[w * STRIDE2];

        const int  X0 = lane, X1 = 32 + lane;       // two item slots
        const bool a1 = (lane < 8);                 // X1 in [32,40)
        int off0 = X0 - 1, off1 = X1 - 1;
        u64 carry0 = 0, carry1 = 0;

        // ---------- gmem prefetch prologue ----------
        float pj0a[PFD], pj0b[PFD], pj1a[PFD], pj1b[PFD];
        int pf0 = off0, pf1 = off1;                 // walk, PFD gates ahead
        u64 xi0_s0 = 0, xi0_s1 = 0, xi01 = 0;
        if (X0 >= 2) xi0_s0 = f2pack(__ldg(p0 + off0), __ldg(p1 + off0));
        if (a1)      xi0_s1 = f2pack(__ldg(p0 + off1), __ldg(p1 + off1));
        if (X0 == 0) xi01   = f2pack(__ldg(p0), __ldg(p1));  // {0,1} special
        #pragma unroll
        for (int d = 0; d < PFD; d++) {
            if (d < X0 - 1) {                       // inB(d) for slot 0
                int c = pf0 + (38 - d);
                pj0a[d] = __ldg(p0 + c); pj0b[d] = __ldg(p1 + c);
            }
            pf0 += (d <= X0 - 1) ? (38 - d) : 1;
            if (a1 && d < X1 - 1) {                 // inB(d) for slot 1
                int c = pf1 + (38 - d);
                pj1a[d] = __ldg(p0 + c); pj1b[d] = __ldg(p1 + c);
            }
            pf1 += (d <= X1 - 1) ? (38 - d) : 1;
        }

        // ---------- rotate: warp-autonomous, frontier-carry, gmem-fed B ----
        #pragma unroll
        for (int g = 0; g < NGATES; g++) {
            u64 cs = s_cs[g];                       // 1 broadcast LDS
            float cf, sf; f2unpack(cf, sf, cs);
            const u64 c2  = f2pack(cf, cf);
            const u64 s2  = f2pack(sf, sf);
            const u64 ns2 = s2 ^ 0x8000000080000000ULL;
            const int bs  = 38 - g;                 // compile-time
            const bool gLast = (g == NGATES - 1);

            #define DOIT(X, OFF, PF, CARRY, PJA, PJB, XI0, ACT)  {          \
                const bool inB = (g < (X) - 1);                             \
                if ((ACT) && (inB || g > (X))) {                            \
                    const int step = inB ? bs : 1;                          \
                    u64* pi = rp + (OFF);                                   \
                    u64 xj = inB ? f2pack(PJA[g % PFD], PJB[g % PFD])       \
                                 : *(pi + 1);                               \
                    u64 xi;                                                 \
                    if (g == 0)            xi = XI0;                        \
                    else if (g == (X) + 1) xi = (g == 1 && (X) == 0)        \
                                                ? xi01 : *pi;               \
                    else                   xi = (CARRY);                    \
                    *pi = f2fma(c2, xi, f2mul(ns2, xj));                    \
                    u64 nj = f2fma(s2, xi, f2mul(c2, xj));                  \
                    (CARRY) = nj;                                           \
                    if (g == (X) - 2 || gLast) *(pi + step) = nj;           \
                }                                                           \
                (OFF) += (g <= (X) - 1) ? bs : 1;                           \
                if (g + PFD <= 38) {                                        \
                    if (g + PFD < (X) - 1) {                                \
                        int c = (PF) + (38 - (g + PFD));                    \
                        PJA[g % PFD] = __ldg(p0 + c);                       \
                        PJB[g % PFD] = __ldg(p1 + c);                       \
                    }                                                       \
                    (PF) += (g + PFD <= (X) - 1) ? (38 - (g + PFD)) : 1;    \
                } }

            DOIT(X0, off0, pf0, carry0, pj0a, pj0b, xi0_s0, true)
            DOIT(X1, off1, pf1, carry1, pj1a, pj1b, xi0_s1, a1)
            #undef DOIT
            __syncwarp();
        }
    }
    __syncthreads();                                // all rows final

    // ---------- transposed store: out[b, col, r0+2pr..+1], STG.64 ---------
    {
        float* dstb = out + (size_t)b * DD * DD + r0;
        #pragma unroll 4
        for (int n = tid; n < NITEMS; n += THREADS) {
            int col = n / NPR;
            int pr  = n - col * NPR;
            u64 v = tile2[pr * STRIDE2 + col];               // LDS.64
            *(u64*)(dstb + (size_t)col * DD + 2 * pr) = v;   // STG.64
        }
    }
}

__global__ __launch_bounds__(THREADS, 2)
void rbs_pass1(const float* __restrict__ in, const float* __restrict__ angles) {
    rbs_body(in, g_tmp, angles);
}

__global__ __launch_bounds__(THREADS, 2)
void rbs_pass2(float* __restrict__ out, const float* __restrict__ angles) {
    rbs_body(g_tmp, out, angles);
}

extern "C" void kernel_launch(void* const* d_in, const int* in_sizes, int n_in,
                              void* d_out, int out_size) {
    const float* input_state = (const float*)d_in[0];  // [64,780,780] f32
    const float* angles      = (const float*)d_in[1];  // [39] f32
    float* out = (float*)d_out;

    const int smem = NPR * STRIDE2 * sizeof(u64);      // 93,720 B dynamic
    cudaFuncSetAttribute(rbs_pass1, cudaFuncAttributeMaxDynamicSharedMemorySize, smem);
    cudaFuncSetAttribute(rbs_pass2, cudaFuncAttributeMaxDynamicSharedMemorySize, smem);

    dim3 grid(NBATCH * NTILES);   // 1664 blocks
    rbs_pass1<<<grid, THREADS, smem>>>(input_state, angles);
    rbs_pass2<<<grid, THREADS, smem>>>(out, angles);
}

// round 17
// speedup vs baseline: 1.2225x; 1.2225x over previous
#include <cuda_runtime.h>

// Dense_RBS_density_3D: rho_out = W rho W^T, W = 39 sparse Givens layers
// (38 disjoint 2x2 column rotations each) on the C(40,2)=780-dim basis.
// K(M) = (M W^T)^T = W M^T applied twice => W rho W^T. Two launches with a
// private __device__ scratch between.
//
// R17 vs R15 (same geometry/ops: float2 row-pairing, frontier carry, 15
// rotate warps, 30-row tiles, 512 thr, 2 CTAs/SM): SYNC-FREE SPLIT ROTATE.
// Dependency analysis: B-phase (g<X-1) reads only originals + own carry; its
// writes are consumed only by A-phases. A-phase (g>X) inputs are all final
// after the B loop; its writes are final (read only by the store). So the 39
// per-gate __syncwarp()s collapse to ONE between a pure-B loop and a pure-A
// loop, and the compiler can pipeline LDS across gates. A-walk is closed
// form: offA = X*(79-X)/2 (= rank(X,X+1)), step 1.

#define DD      780
#define NGATES  39
#define NBATCH  64
#define RROWS   30            // rows per tile
#define NPR     15            // pair-rows (float2 lanes)
#define NTILES  26            // 780 / 30
#define STRIDE2 781           // float2 stride per pair-row (odd)
#define THREADS 512
#define NITEMS  (NPR * DD)    // 11700 store items

__device__ float g_tmp[(size_t)NBATCH * DD * DD];  // 155.7 MB scratch

typedef unsigned long long u64;

__device__ __forceinline__ u64 f2pack(float lo, float hi) {
    u64 r; asm("mov.b64 %0, {%1, %2};" : "=l"(r) : "f"(lo), "f"(hi)); return r;
}
__device__ __forceinline__ void f2unpack(float& lo, float& hi, u64 v) {
    asm("mov.b64 {%0, %1}, %2;" : "=f"(lo), "=f"(hi) : "l"(v));
}
__device__ __forceinline__ u64 f2mul(u64 a, u64 b) {
    u64 r; asm("mul.rn.f32x2 %0, %1, %2;" : "=l"(r) : "l"(a), "l"(b)); return r;
}
__device__ __forceinline__ u64 f2fma(u64 a, u64 b, u64 c) {
    u64 r; asm("fma.rn.f32x2 %0, %1, %2, %3;" : "=l"(r) : "l"(a), "l"(b), "l"(c));
    return r;
}

__device__ __forceinline__ void rbs_body(const float* __restrict__ in,
                                         float* __restrict__ out,
                                         const float* __restrict__ angles) {
    extern __shared__ u64 tile2[];                  // NPR * STRIDE2 float2
    __shared__ u64 s_cs[NGATES];                    // packed (cos, sin)

    const int tid  = threadIdx.x;
    const int w    = tid >> 5;
    const int lane = tid & 31;
    const int b    = blockIdx.x / NTILES;
    const int t    = blockIdx.x - b * NTILES;
    const int r0   = t * RROWS;

    if (tid < NGATES) {
        float th = angles[tid];
        s_cs[tid] = f2pack(cosf(th), sinf(th));
    }
    __syncthreads();                                // trig table visible

    const float* src = in + (size_t)b * DD * DD + (size_t)r0 * DD;

    if (w < NPR) {
        // ---------- warp-local stage: rows 2w, 2w+1 -> own tile region -----
        {
            const float* p0 = src + (size_t)(2 * w) * DD;
            const float* p1 = p0 + DD;
            u64* dst = &tile2[w * STRIDE2];
            #pragma unroll 8
            for (int k = 0; k < 24; k++) {                   // 24*32 = 768
                int c = (k << 5) + lane;
                dst[c] = f2pack(__ldg(p0 + c), __ldg(p1 + c));
            }
            int c = 768 + lane;                              // tail: 12 lanes
            if (c < DD)
                dst[c] = f2pack(__ldg(p0 + c), __ldg(p1 + c));
        }
        __syncwarp();                               // stage -> B visibility

        u64* rp = &tile2[w * STRIDE2];
        const int  X0 = lane, X1 = 32 + lane;       // two item slots
        const bool a1 = (lane < 8);                 // X1 in [32,40)
        u64 carry0 = 0, carry1 = 0;

        // ---------- B loop: gates 0..37, NO syncwarp ----------------------
        // Lane X active for g < X-1: reads original xj at off+ (38-g),
        // writes done *pi = rank(g,X); flush rank(X-1,X) at g == X-2.
        {
            int off0 = X0 - 1, off1 = X1 - 1;
            #pragma unroll
            for (int g = 0; g < NGATES - 1; g++) {
                u64 cs = s_cs[g];
                float cf, sf; f2unpack(cf, sf, cs);
                const u64 c2  = f2pack(cf, cf);
                const u64 s2  = f2pack(sf, sf);
                const u64 ns2 = s2 ^ 0x8000000080000000ULL;
                const int bs  = 38 - g;             // compile-time

                #define BSTEP(X, OFF, CARRY, ACT)  {                       \
                    if ((ACT) && g < (X) - 1) {                            \
                        u64* pi = rp + (OFF);                              \
                        u64 xj = pi[bs];            /* original */         \
                        u64 xi = (g == 0) ? *pi : (CARRY);                 \
                        *pi = f2fma(c2, xi, f2mul(ns2, xj));               \
                        u64 nj = f2fma(s2, xi, f2mul(c2, xj));             \
                        (CARRY) = nj;                                      \
                        if (g == (X) - 2) pi[bs] = nj;   /* flush */       \
                        (OFF) += bs;                                       \
                    } }

                BSTEP(X0, off0, carry0, true)
                BSTEP(X1, off1, carry1, a1)
                #undef BSTEP
            }
        }
        __syncwarp();                               // B outputs -> A inputs

        // ---------- A loop: gates 1..38, NO syncwarp ----------------------
        // Lane X active for g > X: offA = rank(X, g) walks stride 1 from
        // rank(X, X+1) = X*(79-X)/2. Reads xj = pi[1]; resume xi = *pi at
        // g == X+1; writes final *pi; gLast also flushes pi[1].
        {
            int offA0 = (X0 * (79 - X0)) >> 1;
            int offA1 = a1 ? ((X1 * (79 - X1)) >> 1) : 0;
            #pragma unroll
            for (int g = 1; g < NGATES; g++) {
                u64 cs = s_cs[g];
                float cf, sf; f2unpack(cf, sf, cs);
                const u64 c2  = f2pack(cf, cf);
                const u64 s2  = f2pack(sf, sf);
                const u64 ns2 = s2 ^ 0x8000000080000000ULL;
                const bool gLast = (g == NGATES - 1);

                #define ASTEP(X, OFF, CARRY, ACT)  {                       \
                    if ((ACT) && g > (X)) {                                \
                        u64* pi = rp + (OFF);                              \
                        u64 xj = pi[1];                                    \
                        u64 xi = (g == (X) + 1) ? *pi : (CARRY);           \
                        *pi = f2fma(c2, xi, f2mul(ns2, xj));               \
                        u64 nj = f2fma(s2, xi, f2mul(c2, xj));             \
                        (CARRY) = nj;                                      \
                        if (gLast) pi[1] = nj;                             \
                        (OFF) += 1;                                        \
                    } }

                ASTEP(X0, offA0, carry0, true)
                ASTEP(X1, offA1, carry1, a1)
                #undef ASTEP
            }
        }
    }
    __syncthreads();                                // all rows final

    // ---------- transposed store: out[b, col, r0+2pr..+1], STG.64 ---------
    {
        float* dstb = out + (size_t)b * DD * DD + r0;
        #pragma unroll 4
        for (int n = tid; n < NITEMS; n += THREADS) {
            int col = n / NPR;
            int pr  = n - col * NPR;
            u64 v = tile2[pr * STRIDE2 + col];               // LDS.64
            *(u64*)(dstb + (size_t)col * DD + 2 * pr) = v;   // STG.64
        }
    }
}

__global__ __launch_bounds__(THREADS, 2)
void rbs_pass1(const float* __restrict__ in, const float* __restrict__ angles) {
    rbs_body(in, g_tmp, angles);
}

__global__ __launch_bounds__(THREADS, 2)
void rbs_pass2(float* __restrict__ out, const float* __restrict__ angles) {
    rbs_body(g_tmp, out, angles);
}

extern "C" void kernel_launch(void* const* d_in, const int* in_sizes, int n_in,
                              void* d_out, int out_size) {
    const float* input_state = (const float*)d_in[0];  // [64,780,780] f32
    const float* angles      = (const float*)d_in[1];  // [39] f32
    float* out = (float*)d_out;

    const int smem = NPR * STRIDE2 * sizeof(u64);      // 93,720 B dynamic
    cudaFuncSetAttribute(rbs_pass1, cudaFuncAttributeMaxDynamicSharedMemorySize, smem);
    cudaFuncSetAttribute(rbs_pass2, cudaFuncAttributeMaxDynamicSharedMemorySize, smem);

    dim3 grid(NBATCH * NTILES);   // 1664 blocks
    rbs_pass1<<<grid, THREADS, smem>>>(input_state, angles);
    rbs_pass2<<<grid, THREADS, smem>>>(out, angles);
}